// round 8
// baseline (speedup 1.0000x reference)
#include <cuda_runtime.h>
#include <math.h>

#define BB 16384
#define NN 20
#define DD 128
#define HH 4
#define SCALE 0.1020620726159658f /* 1/sqrt(96) */

// ---------------- device scratch ----------------
__device__ float g_qt[(size_t)BB * 1536];   // q-tilde
__device__ float g_c [(size_t)BB * 1536];   // context
__device__ float g_ao[(size_t)BB * 384];    // attn out pre-fc
__device__ float g_pre[(size_t)BB * 384];   // fc+bias+residual (pre-LN)
__device__ float g_Mqk[1536 * 256];         // fused Wq*Wk matrix [j][k]

__device__ __forceinline__ unsigned int tf32cvt(float x) {
    unsigned int u;
    asm("cvt.rna.tf32.f32 %0, %1;" : "=r"(u) : "f"(x));
    return u;
}

// ---------------- prep: M_qk[j][k] = sum_d Wq[h*96+d][keff] * Wk[h*96+d][jj] ----------------
__global__ void __launch_bounds__(256) k_prepm(const float* __restrict__ Wq,
                                               const float* __restrict__ Wk) {
    __shared__ float wk[8 * 96];
    const int tid = threadIdx.x;
    const int j0 = blockIdx.x * 8;
    const int h = j0 / 384;
    const int jj0 = j0 - h * 384;

    for (int i = tid; i < 768; i += 256) {
        int jo = i / 96, d = i - jo * 96;
        wk[jo * 96 + d] = Wk[(size_t)(h * 96 + d) * 384 + jj0 + jo];
    }
    __syncthreads();

    const int k = tid;
    const int keff = (k < 128) ? k : k + 128;
    float acc[8] = {};
    for (int d = 0; d < 96; ++d) {
        float wq = __ldg(&Wq[(size_t)(h * 96 + d) * 384 + keff]);
        #pragma unroll
        for (int jo = 0; jo < 8; ++jo)
            acc[jo] = fmaf(wq, wk[jo * 96 + d], acc[jo]);
    }
    #pragma unroll
    for (int jo = 0; jo < 8; ++jo)
        g_Mqk[(size_t)(j0 + jo) * 256 + k] = acc[jo];
}

// ---------- vectorized fragment mma engine ----------
// A layout (per 32-k tile, per 16-row slab of 544 floats):
//   addr = slab*544 + sub*136 + r'*16 + tig*4 + half*2 + rq   (r'=row&7, rq=(row>>3)&1)
//   -> one LDS.128 per (sub) yields the full m16n8k8 A fragment (a0,a1,a2,a3)
// B layout (per tile): addr = col*36 + sub*8 + tig*2 + half
//   -> one LDS.64 per (nt,sub) yields (b0,b1)
template<int NT>
__device__ __forceinline__ void mma_warp_v(float* acc, const float* aslab, const float* bt,
                                           int grp, int tig) {
    #pragma unroll
    for (int sub = 0; sub < 4; ++sub) {
        float4 av = *(const float4*)&aslab[sub * 136 + grp * 16 + tig * 4];
        unsigned int a0 = __float_as_uint(av.x), a1 = __float_as_uint(av.y);
        unsigned int a2 = __float_as_uint(av.z), a3 = __float_as_uint(av.w);
        #pragma unroll
        for (int nt = 0; nt < NT; ++nt) {
            float2 bv = *(const float2*)&bt[(nt * 8 + grp) * 36 + sub * 8 + tig * 2];
            float* c = acc + nt * 4;
            asm volatile(
                "mma.sync.aligned.m16n8k8.row.col.f32.tf32.tf32.f32 "
                "{%0,%1,%2,%3}, {%4,%5,%6,%7}, {%8,%9}, {%0,%1,%2,%3};"
                : "+f"(c[0]), "+f"(c[1]), "+f"(c[2]), "+f"(c[3])
                : "r"(a0), "r"(a1), "r"(a2), "r"(a3),
                  "r"(__float_as_uint(bv.x)), "r"(__float_as_uint(bv.y)));
        }
    }
}

// global B loader (96 cols x 32 k per tile; 3 float4/thread, coalesced)
#define LOADB(W, COLB, KS, KT)                                                \
    _Pragma("unroll")                                                         \
    for (int jj = 0; jj < 3; ++jj) {                                          \
        int qidx = tid + 256 * jj, col = qidx >> 3, q = qidx & 7;             \
        breg[jj] = *(const float4*)&(W)[(size_t)((COLB) + col) * (KS) + (KT) + q * 4]; \
    }
// stage B into pair-interleaved layout (4 scalar STS per float4, conflict-light)
#define STSB_V(DST)                                                           \
    _Pragma("unroll")                                                         \
    for (int jj = 0; jj < 3; ++jj) {                                          \
        int qidx = tid + 256 * jj, col = qidx >> 3, q = qidx & 7;             \
        float* bp_ = (DST) + col * 36 + (q >> 1) * 8 + (q & 1);               \
        bp_[0] = __uint_as_float(tf32cvt(breg[jj].x));                        \
        bp_[2] = __uint_as_float(tf32cvt(breg[jj].y));                        \
        bp_[4] = __uint_as_float(tf32cvt(breg[jj].z));                        \
        bp_[6] = __uint_as_float(tf32cvt(breg[jj].w));                        \
    }
// stage A (thread (row0=tid>>5, kk=tid&31); rows row0+8j) into quad layout
#define STSA_V(DST, NJ)                                                       \
    _Pragma("unroll")                                                         \
    for (int j = 0; j < (NJ); ++j)                                            \
        (DST)[(j >> 1) * 544 + asub + (j & 1)] = __uint_as_float(tf32cvt(areg[j]));

#define ASUB ((kk >> 3) * 136 + row0 * 16 + (kk & 3) * 4 + ((kk >> 2) & 1) * 2)

// ---------------- k_qt: g_qt[B x 1536] = A_eff[B x 256] @ M_qk^T ----------------
// 64-row blocks; A resident in fragment layout for all 8 K-tiles; B streams 128 tiles.
__global__ void __launch_bounds__(256, 2) k_qt(const float* __restrict__ src,
                                               const float* __restrict__ src_ts,
                                               const float* __restrict__ freq,
                                               const float* __restrict__ phase) {
    extern __shared__ __align__(16) float dynq[];
    float* af = dynq;                       // 8 kt x 2176 (4 slabs x 544)
    float* bf0 = dynq + 17408;              // 3456
    float* bf1 = bf0 + 3456;                // 3456
    float* stss = bf1 + 3456;               // 64
    const int tid = threadIdx.x, lane = tid & 31, wid = tid >> 5;
    const int grp = lane >> 2, tig = lane & 3;
    const int b0 = blockIdx.x * 64;
    const int row0 = tid >> 5, kk = tid & 31;
    const int asub = ASUB;

    if (tid < 64) stss[tid] = src_ts[b0 + tid];
    __syncthreads();

    // stage A (src | time-enc) for all 8 k-tiles, fragment layout
    for (int kt = 0; kt < 8; ++kt) {
        int m = kt * 32 + kk;
        float areg[8];
        if (m < 128) {
            #pragma unroll
            for (int j = 0; j < 8; ++j)
                areg[j] = src[(size_t)(b0 + row0 + 8 * j) * 128 + m];
        } else {
            float f = freq[m - 128], ph = phase[m - 128];
            #pragma unroll
            for (int j = 0; j < 8; ++j)
                areg[j] = __cosf(stss[row0 + 8 * j] * f + ph);
        }
        STSA_V(af + kt * 2176, 8);
    }

    float4 breg[3];
    #define LOADB_QT(T) do { int cq_ = (T) >> 3, kt_ = (T) & 7;               \
        _Pragma("unroll")                                                     \
        for (int jj = 0; jj < 3; ++jj) {                                      \
            int qidx = tid + 256 * jj, col = qidx >> 3, q = qidx & 7;         \
            breg[jj] = *(const float4*)&g_Mqk[(size_t)(cq_ * 96 + col) * 256 + kt_ * 32 + q * 4]; \
        } } while (0)

    LOADB_QT(0);
    STSB_V(bf0);
    __syncthreads();

    // warp = (row slab wid>>1, col half wid&1); NT=6 (48 cols)
    const int aoff = (wid >> 1) * 544;
    const int boff = (wid & 1) * 48 * 36;
    float acc[24] = {};
    for (int t = 0; t < 128; ++t) {
        float* bcur = (t & 1) ? bf1 : bf0;
        float* bnxt = (t & 1) ? bf0 : bf1;
        if (t < 127) LOADB_QT(t + 1);
        mma_warp_v<6>(acc, af + (t & 7) * 2176 + aoff, bcur + boff, grp, tig);
        if (t < 127) STSB_V(bnxt);
        __syncthreads();
        if ((t & 7) == 7) {
            int cq = t >> 3;
            int r0 = b0 + (wid >> 1) * 16 + grp;
            #pragma unroll
            for (int nt = 0; nt < 6; ++nt) {
                int col = cq * 96 + (wid & 1) * 48 + nt * 8 + tig * 2;
                *(float2*)&g_qt[(size_t)r0 * 1536 + col] =
                    make_float2(acc[nt*4+0], acc[nt*4+1]);
                *(float2*)&g_qt[(size_t)(r0 + 8) * 1536 + col] =
                    make_float2(acc[nt*4+2], acc[nt*4+3]);
                acc[nt*4+0] = 0.f; acc[nt*4+1] = 0.f;
                acc[nt*4+2] = 0.f; acc[nt*4+3] = 0.f;
            }
        }
    }
    #undef LOADB_QT
}

// ---------------- attention core: one block per batch element ----------------
__global__ void __launch_bounds__(256) k_attn(const float* __restrict__ seq,
                                              const float* __restrict__ seq_e,
                                              const float* __restrict__ seq_ts,
                                              const unsigned int* __restrict__ mask,
                                              const float* __restrict__ freq,
                                              const float* __restrict__ phase,
                                              float* __restrict__ attn_out) {
    __shared__ float kin[NN * 384];
    __shared__ float qts[1536];
    __shared__ float sc[HH][NN];
    __shared__ float pp[HH][NN];
    const int b = blockIdx.x;
    const int tid = threadIdx.x;
    const int w = tid >> 5, lane = tid & 31;

    const float4* seq4   = (const float4*)seq;
    const float4* seq_e4 = (const float4*)seq_e;
    for (int idx = tid; idx < NN * 32; idx += 256) {
        int n = idx >> 5, q = idx & 31;
        float4 a = seq4  [((size_t)b * NN + n) * 32 + q];
        float4 e = seq_e4[((size_t)b * NN + n) * 32 + q];
        *(float4*)&kin[n * 384 + q * 4]       = a;
        *(float4*)&kin[n * 384 + 128 + q * 4] = e;
    }
    for (int idx = tid; idx < NN * 128; idx += 256) {
        int n = idx >> 7, d = idx & 127;
        kin[n * 384 + 256 + d] = __cosf(seq_ts[b * NN + n] * freq[d] + phase[d]);
    }
    const float4* qt4 = (const float4*)(g_qt + (size_t)b * 1536);
    for (int idx = tid; idx < 384; idx += 256)
        *(float4*)&qts[idx * 4] = qt4[idx];
    __syncthreads();

    for (int p = w; p < HH * NN; p += 8) {
        int h = p / NN, n = p - h * NN;
        float partial = 0.f;
        #pragma unroll
        for (int t = 0; t < 12; ++t)
            partial = fmaf(qts[h * 384 + lane + 32 * t], kin[n * 384 + lane + 32 * t], partial);
        #pragma unroll
        for (int off = 16; off; off >>= 1)
            partial += __shfl_xor_sync(0xffffffffu, partial, off);
        if (lane == 0) {
            float s = partial * SCALE;
            if (mask[b * NN + n] != 0u) s = -1.0e10f;
            sc[h][n] = s;
        }
    }
    __syncthreads();

    if (w < HH) {
        float v = (lane < NN) ? sc[w][lane] : -3.0e38f;
        float mx = v;
        #pragma unroll
        for (int off = 16; off; off >>= 1)
            mx = fmaxf(mx, __shfl_xor_sync(0xffffffffu, mx, off));
        float e = (lane < NN) ? expf(v - mx) : 0.f;
        float s = e;
        #pragma unroll
        for (int off = 16; off; off >>= 1)
            s += __shfl_xor_sync(0xffffffffu, s, off);
        float prob = e / s;
        if (lane < NN) {
            pp[w][lane] = prob;
            attn_out[((size_t)w * BB + b) * NN + lane] = prob;
        }
    }
    __syncthreads();

    for (int idx = tid; idx < 1536; idx += 256) {
        int h = idx / 384, j = idx - h * 384;
        float s = 0.f;
        #pragma unroll
        for (int n = 0; n < NN; ++n)
            s = fmaf(pp[h][n], kin[n * 384 + j], s);
        g_c[(size_t)b * 1536 + idx] = s;
    }
}

// ---------------- k_vout: g_ao head slab = g_c_h[B x 384] @ Wv_h^T ----------------
__global__ void __launch_bounds__(256, 2) k_vout(const float* __restrict__ Wv) {
    extern __shared__ __align__(16) float dynv[];
    float* saf0 = dynv;            // 4352
    float* saf1 = dynv + 4352;
    float* sbt0 = dynv + 8704;     // 3456
    float* sbt1 = sbt0 + 3456;
    const int tid = threadIdx.x, lane = tid & 31, wid = tid >> 5;
    const int grp = lane >> 2, tig = lane & 3;
    const int bt = blockIdx.x >> 2, h = blockIdx.x & 3, b0 = bt * 128;
    const int row0 = tid >> 5, kk = tid & 31;
    const int asub = ASUB;

    float areg[16]; float4 breg[3];
    #define LOADA_V(KT)                                                        \
        _Pragma("unroll")                                                      \
        for (int j = 0; j < 16; ++j)                                           \
            areg[j] = g_c[(size_t)(b0 + row0 + 8 * j) * 1536 + h * 384 + (KT) + kk];

    LOADA_V(0); LOADB(Wv, h * 96, 384, 0);
    STSA_V(saf0, 16); STSB_V(sbt0);
    __syncthreads();
    float acc[48] = {};
    for (int t = 0; t < 12; ++t) {
        float* sa = (t & 1) ? saf1 : saf0;
        float* sb = (t & 1) ? sbt1 : sbt0;
        float* na = (t & 1) ? saf0 : saf1;
        float* nb = (t & 1) ? sbt0 : sbt1;
        if (t < 11) { LOADA_V((t + 1) * 32); LOADB(Wv, h * 96, 384, (t + 1) * 32); }
        mma_warp_v<12>(acc, sa + wid * 544, sb, grp, tig);
        if (t < 11) { STSA_V(na, 16); STSB_V(nb); }
        __syncthreads();
    }
    const int r0 = b0 + wid * 16 + grp;
    #pragma unroll
    for (int nt = 0; nt < 12; ++nt) {
        int col = h * 96 + nt * 8 + tig * 2;
        *(float2*)&g_ao[(size_t)r0 * 384 + col]       = make_float2(acc[nt*4+0], acc[nt*4+1]);
        *(float2*)&g_ao[(size_t)(r0 + 8) * 384 + col] = make_float2(acc[nt*4+2], acc[nt*4+3]);
    }
    #undef LOADA_V
}

// ---------------- k_fc: g_pre = g_ao @ fc_w^T + b + residual ----------------
__global__ void __launch_bounds__(256, 2) k_fc(const float* __restrict__ src,
                                               const float* __restrict__ src_ts,
                                               const float* __restrict__ freq,
                                               const float* __restrict__ phase,
                                               const float* __restrict__ fc_w,
                                               const float* __restrict__ fc_b) {
    extern __shared__ __align__(16) float dynf[];
    float* saf0 = dynf;
    float* saf1 = dynf + 4352;
    float* sbt0 = dynf + 8704;
    float* sbt1 = sbt0 + 3456;
    const int tid = threadIdx.x, lane = tid & 31, wid = tid >> 5;
    const int grp = lane >> 2, tig = lane & 3;
    const int bt = blockIdx.x >> 2, cq = blockIdx.x & 3;
    const int b0 = bt * 128, c0 = cq * 96;
    const int row0 = tid >> 5, kk = tid & 31;
    const int asub = ASUB;

    float areg[16]; float4 breg[3];
    #define LOADA_F(KT)                                                        \
        _Pragma("unroll")                                                      \
        for (int j = 0; j < 16; ++j)                                           \
            areg[j] = g_ao[(size_t)(b0 + row0 + 8 * j) * 384 + (KT) + kk];

    LOADA_F(0); LOADB(fc_w, c0, 384, 0);
    STSA_V(saf0, 16); STSB_V(sbt0);
    __syncthreads();
    float acc[48] = {};
    for (int t = 0; t < 12; ++t) {
        float* sa = (t & 1) ? saf1 : saf0;
        float* sb = (t & 1) ? sbt1 : sbt0;
        float* na = (t & 1) ? saf0 : saf1;
        float* nb = (t & 1) ? sbt0 : sbt1;
        if (t < 11) { LOADA_F((t + 1) * 32); LOADB(fc_w, c0, 384, (t + 1) * 32); }
        mma_warp_v<12>(acc, sa + wid * 544, sb, grp, tig);
        if (t < 11) { STSA_V(na, 16); STSB_V(nb); }
        __syncthreads();
    }
    const int r0 = b0 + wid * 16 + grp;
    const float ts0 = src_ts[r0], ts1 = src_ts[r0 + 8];
    #pragma unroll
    for (int nt = 0; nt < 12; ++nt) {
        #pragma unroll
        for (int cc = 0; cc < 2; ++cc) {
            int col = c0 + nt * 8 + tig * 2 + cc;
            float v0 = acc[nt*4 + cc]     + fc_b[col];
            float v1 = acc[nt*4 + 2 + cc] + fc_b[col];
            if (col < 128) {
                v0 += src[(size_t)r0 * 128 + col];
                v1 += src[(size_t)(r0 + 8) * 128 + col];
            } else if (col >= 256) {
                int d = col - 256;
                float f = freq[d], ph = phase[d];
                v0 += __cosf(ts0 * f + ph);
                v1 += __cosf(ts1 * f + ph);
            }
            g_pre[(size_t)r0 * 384 + col]       = v0;
            g_pre[(size_t)(r0 + 8) * 384 + col] = v1;
        }
    }
    #undef LOADA_F
}

// ---------------- k_mlp: two-pass LN + tensor-core MLP, 64 rows/block ----------------
__global__ void __launch_bounds__(256) k_mlp(const float* __restrict__ src,
                                             const float* __restrict__ ln_g,
                                             const float* __restrict__ ln_b,
                                             const float* __restrict__ m1_w,
                                             const float* __restrict__ m1_b,
                                             const float* __restrict__ m2_w,
                                             const float* __restrict__ m2_b,
                                             float* __restrict__ y) {
    extern __shared__ __align__(16) float dynm[];
    float* saf  = dynm;                 // 2304 (64 rows, stride-36 scalar layout)
    float* sbt  = saf + 64 * 36;        // 4608
    float* hst  = sbt + 128 * 36;       // 4 x 2304
    float* smu  = hst + 4 * 2304;       // 64
    float* sinv = smu + 64;             // 64
    const int tid = threadIdx.x, lane = tid & 31, wid = tid >> 5;
    const int b0 = blockIdx.x * 64;
    const int kk = tid & 31, row0 = tid >> 5;

    for (int rr = 0; rr < 8; ++rr) {
        int row = wid * 8 + rr;
        const float* pr = g_pre + (size_t)(b0 + row) * 384;
        float s1 = 0.f, s2 = 0.f;
        #pragma unroll
        for (int t = 0; t < 12; ++t) {
            float v = pr[lane + 32 * t];
            s1 += v; s2 = fmaf(v, v, s2);
        }
        #pragma unroll
        for (int off = 16; off; off >>= 1) {
            s1 += __shfl_xor_sync(0xffffffffu, s1, off);
            s2 += __shfl_xor_sync(0xffffffffu, s2, off);
        }
        if (lane == 0) {
            float mu = s1 * (1.f / 384.f);
            float var = s2 * (1.f / 384.f) - mu * mu;
            smu[row] = mu;
            sinv[row] = rsqrtf(var + 1e-5f);
        }
    }
    __syncthreads();

    float areg[8]; float4 breg[4];
    #define LOADB4(W, KS, KT)                                                  \
        _Pragma("unroll")                                                      \
        for (int jj = 0; jj < 4; ++jj) {                                       \
            int qidx = tid + 256 * jj, col = qidx >> 3, q = qidx & 7;          \
            breg[jj] = *(const float4*)&(W)[(size_t)col * (KS) + (KT) + q * 4]; \
        }
    #define STSB4()                                                            \
        _Pragma("unroll")                                                      \
        for (int jj = 0; jj < 4; ++jj) {                                       \
            int qidx = tid + 256 * jj, col = qidx >> 3, q = qidx & 7;          \
            float4 v = breg[jj];                                               \
            v.x = __uint_as_float(tf32cvt(v.x)); v.y = __uint_as_float(tf32cvt(v.y)); \
            v.z = __uint_as_float(tf32cvt(v.z)); v.w = __uint_as_float(tf32cvt(v.w)); \
            *(float4*)&sbt[col * 36 + q * 4] = v;                              \
        }
    #define LOADA_X(KT) do {                                                   \
        int k_ = (KT) + kk;                                                    \
        if (k_ < 384) {                                                        \
            _Pragma("unroll")                                                  \
            for (int j = 0; j < 8; ++j)                                        \
                areg[j] = g_pre[(size_t)(b0 + row0 + 8 * j) * 384 + k_];       \
        } else {                                                               \
            int d_ = k_ - 384;                                                 \
            _Pragma("unroll")                                                  \
            for (int j = 0; j < 8; ++j)                                        \
                areg[j] = src[(size_t)(b0 + row0 + 8 * j) * 128 + d_];         \
        } } while (0)
    #define STSA_X(KT) do {                                                    \
        int k_ = (KT) + kk;                                                    \
        if (k_ < 384) {                                                        \
            float lng = ln_g[k_], lnb = ln_b[k_];                              \
            _Pragma("unroll")                                                  \
            for (int j = 0; j < 8; ++j) {                                      \
                int row = row0 + 8 * j;                                        \
                float v = (areg[j] - smu[row]) * sinv[row] * lng + lnb;        \
                saf[row * 36 + kk] = __uint_as_float(tf32cvt(v));              \
            }                                                                  \
        } else {                                                               \
            _Pragma("unroll")                                                  \
            for (int j = 0; j < 8; ++j)                                        \
                saf[(row0 + 8 * j) * 36 + kk] = __uint_as_float(tf32cvt(areg[j])); \
        } } while (0)

    const int grp = lane >> 2, tig = lane & 3;
    const int rslab = (wid >> 1) * 16, chalf = (wid & 1) * 64;
    const int r0 = rslab + grp;

    // scalar-layout fragment loads for the MLP (unchanged engine from R7)
    #define MMA_SCALAR(ACC, SA, SB, NTC)                                       \
        _Pragma("unroll")                                                      \
        for (int sub = 0; sub < 4; ++sub) {                                    \
            const int kb = sub * 8;                                            \
            const float* ap = (SA) + grp * 36 + kb + tig;                      \
            unsigned int a0 = __float_as_uint(ap[0]);                          \
            unsigned int a1 = __float_as_uint(ap[8 * 36]);                     \
            unsigned int a2 = __float_as_uint(ap[4]);                          \
            unsigned int a3 = __float_as_uint(ap[8 * 36 + 4]);                 \
            _Pragma("unroll")                                                  \
            for (int nt = 0; nt < (NTC); ++nt) {                               \
                const float* bp = (SB) + (nt * 8 + grp) * 36 + kb + tig;       \
                unsigned int b0_ = __float_as_uint(bp[0]);                     \
                unsigned int b1_ = __float_as_uint(bp[4]);                     \
                float* c = (ACC) + nt * 4;                                     \
                asm volatile(                                                  \
                    "mma.sync.aligned.m16n8k8.row.col.f32.tf32.tf32.f32 "      \
                    "{%0,%1,%2,%3}, {%4,%5,%6,%7}, {%8,%9}, {%0,%1,%2,%3};"    \
                    : "+f"(c[0]), "+f"(c[1]), "+f"(c[2]), "+f"(c[3])           \
                    : "r"(a0), "r"(a1), "r"(a2), "r"(a3), "r"(b0_), "r"(b1_)); \
            }                                                                  \
        }

    LOADA_X(0); LOADB4(m1_w, 512, 0);
    float acc[32] = {};
    for (int t = 0; t < 16; ++t) {
        __syncthreads();
        STSA_X(t * 32); STSB4();
        __syncthreads();
        if (t < 15) { LOADA_X((t + 1) * 32); LOADB4(m1_w, 512, (t + 1) * 32); }
        MMA_SCALAR(acc, saf + rslab * 36, sbt + chalf * 36, 8)
    }
    #pragma unroll
    for (int nt = 0; nt < 8; ++nt) {
        int col = chalf + nt * 8 + tig * 2;
        float b1a = m1_b[col], b1b = m1_b[col + 1];
        float* hb = hst + (col >> 5) * 2304 + (col & 31);
        hb[r0 * 36]           = __uint_as_float(tf32cvt(fmaxf(acc[nt*4+0] + b1a, 0.f)));
        hb[r0 * 36 + 1]       = __uint_as_float(tf32cvt(fmaxf(acc[nt*4+1] + b1b, 0.f)));
        hb[(r0 + 8) * 36]     = __uint_as_float(tf32cvt(fmaxf(acc[nt*4+2] + b1a, 0.f)));
        hb[(r0 + 8) * 36 + 1] = __uint_as_float(tf32cvt(fmaxf(acc[nt*4+3] + b1b, 0.f)));
    }
    #pragma unroll
    for (int i = 0; i < 32; ++i) acc[i] = 0.f;

    for (int t = 0; t < 4; ++t) {
        LOADB4(m2_w, 128, t * 32);
        __syncthreads();
        STSB4();
        __syncthreads();
        MMA_SCALAR(acc, hst + t * 2304 + rslab * 36, sbt + chalf * 36, 8)
    }
    #pragma unroll
    for (int nt = 0; nt < 8; ++nt) {
        int col = chalf + nt * 8 + tig * 2;
        float b2a = m2_b[col], b2b = m2_b[col + 1];
        *(float2*)&y[(size_t)(b0 + r0) * 128 + col] =
            make_float2(acc[nt*4+0] + b2a, acc[nt*4+1] + b2b);
        *(float2*)&y[(size_t)(b0 + r0 + 8) * 128 + col] =
            make_float2(acc[nt*4+2] + b2a, acc[nt*4+3] + b2b);
    }
    #undef LOADB4
    #undef STSB4
    #undef LOADA_X
    #undef STSA_X
    #undef MMA_SCALAR
}

// ---------------- launch ----------------
extern "C" void kernel_launch(void* const* d_in, const int* in_sizes, int n_in,
                              void* d_out, int out_size) {
    const float* src    = (const float*)d_in[0];
    const float* seq    = (const float*)d_in[1];
    const float* seq_e  = (const float*)d_in[2];
    const float* src_ts = (const float*)d_in[3];
    const float* seq_ts = (const float*)d_in[4];
    const unsigned int* mask = (const unsigned int*)d_in[5];
    const float* freq   = (const float*)d_in[6];
    const float* phase  = (const float*)d_in[7];
    const float* Wq     = (const float*)d_in[8];
    const float* Wk     = (const float*)d_in[9];
    const float* Wv     = (const float*)d_in[10];
    const float* fc_w   = (const float*)d_in[11];
    const float* fc_b   = (const float*)d_in[12];
    const float* ln_g   = (const float*)d_in[13];
    const float* ln_b   = (const float*)d_in[14];
    const float* m1_w   = (const float*)d_in[15];
    const float* m1_b   = (const float*)d_in[16];
    const float* m2_w   = (const float*)d_in[17];
    const float* m2_b   = (const float*)d_in[18];

    float* y_out = (float*)d_out;
    float* attn_out = y_out + (size_t)BB * DD;

    const int qt_smem   = (17408 + 2 * 3456 + 64) * 4;           // 97536
    const int gemm_smem = (2 * 4352 + 2 * 3456) * 4;             // 62464
    const int mlp_smem  = (2304 + 4608 + 4 * 2304 + 128) * 4;    // 65024
    cudaFuncSetAttribute(k_qt,   cudaFuncAttributeMaxDynamicSharedMemorySize, qt_smem);
    cudaFuncSetAttribute(k_vout, cudaFuncAttributeMaxDynamicSharedMemorySize, gemm_smem);
    cudaFuncSetAttribute(k_fc,   cudaFuncAttributeMaxDynamicSharedMemorySize, gemm_smem);
    cudaFuncSetAttribute(k_mlp,  cudaFuncAttributeMaxDynamicSharedMemorySize, mlp_smem);

    k_prepm <<<192, 256>>>(Wq, Wk);
    k_qt    <<<256, 256, qt_smem>>>(src, src_ts, freq, phase);
    k_attn  <<<BB, 256>>>(seq, seq_e, seq_ts, mask, freq, phase, attn_out);
    k_vout  <<<512, 256, gemm_smem>>>(Wv);
    k_fc    <<<512, 256, gemm_smem>>>(src, src_ts, freq, phase, fc_w, fc_b);
    k_mlp   <<<256, 256, mlp_smem>>>(src, ln_g, ln_b, m1_w, m1_b, m2_w, m2_b, y_out);
}

// round 9
// speedup vs baseline: 1.2083x; 1.2083x over previous
#include <cuda_runtime.h>
#include <math.h>

#define BB 16384
#define NN 20
#define DD 128
#define HH 4
#define SCALE 0.1020620726159658f /* 1/sqrt(96) */

// ---------------- device scratch ----------------
__device__ float g_qt[(size_t)BB * 1536];   // q-tilde
__device__ float g_c [(size_t)BB * 1536];   // context
__device__ float g_ao[(size_t)BB * 384];    // attn out pre-fc
__device__ float g_pre[(size_t)BB * 384];   // fc+bias+residual (pre-LN)
__device__ float g_Mqk[1536 * 256];         // fused Wq*Wk matrix [j][k]

__device__ __forceinline__ unsigned int tf32cvt(float x) {
    unsigned int u;
    asm("cvt.rna.tf32.f32 %0, %1;" : "=r"(u) : "f"(x));
    return u;
}

// ---------------- prep: M_qk[j][k] = sum_d Wq[h*96+d][keff] * Wk[h*96+d][jj] ----------------
__global__ void __launch_bounds__(256) k_prepm(const float* __restrict__ Wq,
                                               const float* __restrict__ Wk) {
    __shared__ float wk[8 * 96];
    const int tid = threadIdx.x;
    const int j0 = blockIdx.x * 8;
    const int h = j0 / 384;
    const int jj0 = j0 - h * 384;

    for (int i = tid; i < 768; i += 256) {
        int jo = i / 96, d = i - jo * 96;
        wk[jo * 96 + d] = Wk[(size_t)(h * 96 + d) * 384 + jj0 + jo];
    }
    __syncthreads();

    const int k = tid;
    const int keff = (k < 128) ? k : k + 128;
    float acc[8] = {};
    for (int d = 0; d < 96; ++d) {
        float wq = __ldg(&Wq[(size_t)(h * 96 + d) * 384 + keff]);
        #pragma unroll
        for (int jo = 0; jo < 8; ++jo)
            acc[jo] = fmaf(wq, wk[jo * 96 + d], acc[jo]);
    }
    #pragma unroll
    for (int jo = 0; jo < 8; ++jo)
        g_Mqk[(size_t)(j0 + jo) * 256 + k] = acc[jo];
}

// ---------- warp mma engine: 32 rows x NT*8 cols; B fragments reused for 2 A slabs ----------
// sa: warp's A rows [32][stride 36]; sbt: B cols [..][stride 36] (tf32 bits)
// acc layout: [nt*4] for rows 0..15 slab, [(NT+nt)*4] for rows 16..31 slab.
template<int NT>
__device__ __forceinline__ void mma_warp2(float* acc, const float* sa, const float* sbt,
                                          int lane) {
    const int grp = lane >> 2, tig = lane & 3;
    #pragma unroll
    for (int sub = 0; sub < 4; ++sub) {
        const int kb = sub * 8;
        const float* ap0 = sa + grp * 36 + kb + tig;
        const float* ap1 = ap0 + 16 * 36;
        unsigned int a00 = __float_as_uint(ap0[0]);
        unsigned int a01 = __float_as_uint(ap0[8 * 36]);
        unsigned int a02 = __float_as_uint(ap0[4]);
        unsigned int a03 = __float_as_uint(ap0[8 * 36 + 4]);
        unsigned int a10 = __float_as_uint(ap1[0]);
        unsigned int a11 = __float_as_uint(ap1[8 * 36]);
        unsigned int a12 = __float_as_uint(ap1[4]);
        unsigned int a13 = __float_as_uint(ap1[8 * 36 + 4]);
        #pragma unroll
        for (int nt = 0; nt < NT; ++nt) {
            const float* bp = sbt + (nt * 8 + grp) * 36 + kb + tig;
            unsigned int b0 = __float_as_uint(bp[0]);
            unsigned int b1 = __float_as_uint(bp[4]);
            float* c0 = acc + nt * 4;
            asm volatile(
                "mma.sync.aligned.m16n8k8.row.col.f32.tf32.tf32.f32 "
                "{%0,%1,%2,%3}, {%4,%5,%6,%7}, {%8,%9}, {%0,%1,%2,%3};"
                : "+f"(c0[0]), "+f"(c0[1]), "+f"(c0[2]), "+f"(c0[3])
                : "r"(a00), "r"(a01), "r"(a02), "r"(a03), "r"(b0), "r"(b1));
            float* c1 = acc + (NT + nt) * 4;
            asm volatile(
                "mma.sync.aligned.m16n8k8.row.col.f32.tf32.tf32.f32 "
                "{%0,%1,%2,%3}, {%4,%5,%6,%7}, {%8,%9}, {%0,%1,%2,%3};"
                : "+f"(c1[0]), "+f"(c1[1]), "+f"(c1[2]), "+f"(c1[3])
                : "r"(a10), "r"(a11), "r"(a12), "r"(a13), "r"(b0), "r"(b1));
        }
    }
}

// B loader/stager: 96 cols variant (3 float4/thread)
#define LOADB(W, COLB, KS, KT)                                                \
    _Pragma("unroll")                                                         \
    for (int jj = 0; jj < 3; ++jj) {                                          \
        int qidx = tid + 256 * jj, col = qidx >> 3, q = qidx & 7;             \
        breg[jj] = *(const float4*)&(W)[(size_t)((COLB) + col) * (KS) + (KT) + q * 4]; \
    }
#define STSB()                                                                \
    _Pragma("unroll")                                                         \
    for (int jj = 0; jj < 3; ++jj) {                                          \
        int qidx = tid + 256 * jj, col = qidx >> 3, q = qidx & 7;             \
        float4 v = breg[jj];                                                  \
        v.x = __uint_as_float(tf32cvt(v.x)); v.y = __uint_as_float(tf32cvt(v.y)); \
        v.z = __uint_as_float(tf32cvt(v.z)); v.w = __uint_as_float(tf32cvt(v.w)); \
        *(float4*)&sbt[col * 36 + q * 4] = v;                                 \
    }
#define STSA()                                                                \
    _Pragma("unroll")                                                         \
    for (int j = 0; j < 16; ++j)                                              \
        saf[(row0 + 8 * j) * 36 + kk] = __uint_as_float(tf32cvt(areg[j]));

// ---------------- k_qt: g_qt[B x 1536] = A_eff[B x 256] @ M_qk^T ----------------
__global__ void __launch_bounds__(256, 2) k_qt(const float* __restrict__ src,
                                               const float* __restrict__ src_ts,
                                               const float* __restrict__ freq,
                                               const float* __restrict__ phase) {
    __shared__ __align__(16) float saf[128 * 36];
    __shared__ __align__(16) float sbt[96 * 36];
    __shared__ float sts[128];
    const int tid = threadIdx.x, lane = tid & 31, wid = tid >> 5;
    const int bt = blockIdx.x >> 4, cq = blockIdx.x & 15;
    const int b0 = bt * 128, c0 = cq * 96;
    const int kk = tid & 31, row0 = tid >> 5;
    const int rslab = (wid >> 1) * 32, chalf = (wid & 1) * 48;

    if (tid < 128) sts[tid] = src_ts[b0 + tid];
    __syncthreads();

    float areg[16]; float4 breg[3];
    #define LOADA_QT(KT) do {                                                 \
        int m = (KT) + kk;                                                    \
        if (m < 128) {                                                        \
            _Pragma("unroll")                                                 \
            for (int j = 0; j < 16; ++j)                                      \
                areg[j] = src[(size_t)(b0 + row0 + 8 * j) * 128 + m];         \
        } else {                                                              \
            float f = freq[m - 128], ph = phase[m - 128];                     \
            _Pragma("unroll")                                                 \
            for (int j = 0; j < 16; ++j)                                      \
                areg[j] = __cosf(sts[row0 + 8 * j] * f + ph);                 \
        } } while (0)

    LOADA_QT(0); LOADB(g_Mqk, c0, 256, 0);
    float acc[48] = {};
    for (int t = 0; t < 8; ++t) {
        __syncthreads();
        STSA(); STSB();
        __syncthreads();
        if (t < 7) { LOADA_QT((t + 1) * 32); LOADB(g_Mqk, c0, 256, (t + 1) * 32); }
        mma_warp2<6>(acc, saf + rslab * 36, sbt + chalf * 36, lane);
    }
    const int grp = lane >> 2, tig = lane & 3;
    const int r0 = b0 + rslab + grp;
    #pragma unroll
    for (int nt = 0; nt < 6; ++nt) {
        int j = c0 + chalf + nt * 8 + tig * 2;
        *(float2*)&g_qt[(size_t)r0 * 1536 + j]        = make_float2(acc[nt*4+0], acc[nt*4+1]);
        *(float2*)&g_qt[(size_t)(r0 + 8) * 1536 + j]  = make_float2(acc[nt*4+2], acc[nt*4+3]);
        *(float2*)&g_qt[(size_t)(r0 + 16) * 1536 + j] = make_float2(acc[(6+nt)*4+0], acc[(6+nt)*4+1]);
        *(float2*)&g_qt[(size_t)(r0 + 24) * 1536 + j] = make_float2(acc[(6+nt)*4+2], acc[(6+nt)*4+3]);
    }
    #undef LOADA_QT
}

// ---------------- attention core: one block per batch element ----------------
__global__ void __launch_bounds__(256) k_attn(const float* __restrict__ seq,
                                              const float* __restrict__ seq_e,
                                              const float* __restrict__ seq_ts,
                                              const unsigned int* __restrict__ mask,
                                              const float* __restrict__ freq,
                                              const float* __restrict__ phase,
                                              float* __restrict__ attn_out) {
    __shared__ float kin[NN * 384];
    __shared__ float qts[1536];
    __shared__ float sc[HH][NN];
    __shared__ float pp[HH][NN];
    const int b = blockIdx.x;
    const int tid = threadIdx.x;
    const int w = tid >> 5, lane = tid & 31;

    const float4* seq4   = (const float4*)seq;
    const float4* seq_e4 = (const float4*)seq_e;
    for (int idx = tid; idx < NN * 32; idx += 256) {
        int n = idx >> 5, q = idx & 31;
        float4 a = seq4  [((size_t)b * NN + n) * 32 + q];
        float4 e = seq_e4[((size_t)b * NN + n) * 32 + q];
        *(float4*)&kin[n * 384 + q * 4]       = a;
        *(float4*)&kin[n * 384 + 128 + q * 4] = e;
    }
    for (int idx = tid; idx < NN * 128; idx += 256) {
        int n = idx >> 7, d = idx & 127;
        kin[n * 384 + 256 + d] = __cosf(seq_ts[b * NN + n] * freq[d] + phase[d]);
    }
    const float4* qt4 = (const float4*)(g_qt + (size_t)b * 1536);
    for (int idx = tid; idx < 384; idx += 256)
        *(float4*)&qts[idx * 4] = qt4[idx];
    __syncthreads();

    for (int p = w; p < HH * NN; p += 8) {
        int h = p / NN, n = p - h * NN;
        float partial = 0.f;
        #pragma unroll
        for (int t = 0; t < 12; ++t)
            partial = fmaf(qts[h * 384 + lane + 32 * t], kin[n * 384 + lane + 32 * t], partial);
        #pragma unroll
        for (int off = 16; off; off >>= 1)
            partial += __shfl_xor_sync(0xffffffffu, partial, off);
        if (lane == 0) {
            float s = partial * SCALE;
            if (mask[b * NN + n] != 0u) s = -1.0e10f;
            sc[h][n] = s;
        }
    }
    __syncthreads();

    if (w < HH) {
        float v = (lane < NN) ? sc[w][lane] : -3.0e38f;
        float mx = v;
        #pragma unroll
        for (int off = 16; off; off >>= 1)
            mx = fmaxf(mx, __shfl_xor_sync(0xffffffffu, mx, off));
        float e = (lane < NN) ? expf(v - mx) : 0.f;
        float s = e;
        #pragma unroll
        for (int off = 16; off; off >>= 1)
            s += __shfl_xor_sync(0xffffffffu, s, off);
        float prob = e / s;
        if (lane < NN) {
            pp[w][lane] = prob;
            attn_out[((size_t)w * BB + b) * NN + lane] = prob;
        }
    }
    __syncthreads();

    for (int idx = tid; idx < 1536; idx += 256) {
        int h = idx / 384, j = idx - h * 384;
        float s = 0.f;
        #pragma unroll
        for (int n = 0; n < NN; ++n)
            s = fmaf(pp[h][n], kin[n * 384 + j], s);
        g_c[(size_t)b * 1536 + idx] = s;
    }
}

// ---------------- k_vout: g_ao head slab = g_c_h[B x 384] @ Wv_h^T ----------------
__global__ void __launch_bounds__(256, 2) k_vout(const float* __restrict__ Wv) {
    __shared__ __align__(16) float saf[128 * 36];
    __shared__ __align__(16) float sbt[96 * 36];
    const int tid = threadIdx.x, lane = tid & 31, wid = tid >> 5;
    const int bt = blockIdx.x >> 2, h = blockIdx.x & 3;
    const int b0 = bt * 128;
    const int kk = tid & 31, row0 = tid >> 5;
    const int rslab = (wid >> 1) * 32, chalf = (wid & 1) * 48;

    float areg[16]; float4 breg[3];
    #define LOADA_V(KT)                                                        \
        _Pragma("unroll")                                                      \
        for (int j = 0; j < 16; ++j)                                           \
            areg[j] = g_c[(size_t)(b0 + row0 + 8 * j) * 1536 + h * 384 + (KT) + kk];

    LOADA_V(0); LOADB(Wv, h * 96, 384, 0);
    float acc[48] = {};
    for (int t = 0; t < 12; ++t) {
        __syncthreads();
        STSA(); STSB();
        __syncthreads();
        if (t < 11) { LOADA_V((t + 1) * 32); LOADB(Wv, h * 96, 384, (t + 1) * 32); }
        mma_warp2<6>(acc, saf + rslab * 36, sbt + chalf * 36, lane);
    }
    const int grp = lane >> 2, tig = lane & 3;
    const int r0 = b0 + rslab + grp;
    #pragma unroll
    for (int nt = 0; nt < 6; ++nt) {
        int col = h * 96 + chalf + nt * 8 + tig * 2;
        *(float2*)&g_ao[(size_t)r0 * 384 + col]        = make_float2(acc[nt*4+0], acc[nt*4+1]);
        *(float2*)&g_ao[(size_t)(r0 + 8) * 384 + col]  = make_float2(acc[nt*4+2], acc[nt*4+3]);
        *(float2*)&g_ao[(size_t)(r0 + 16) * 384 + col] = make_float2(acc[(6+nt)*4+0], acc[(6+nt)*4+1]);
        *(float2*)&g_ao[(size_t)(r0 + 24) * 384 + col] = make_float2(acc[(6+nt)*4+2], acc[(6+nt)*4+3]);
    }
    #undef LOADA_V
}

// ---------------- k_fc: g_pre = g_ao @ fc_w^T + b + residual ----------------
__global__ void __launch_bounds__(256, 2) k_fc(const float* __restrict__ src,
                                               const float* __restrict__ src_ts,
                                               const float* __restrict__ freq,
                                               const float* __restrict__ phase,
                                               const float* __restrict__ fc_w,
                                               const float* __restrict__ fc_b) {
    __shared__ __align__(16) float saf[128 * 36];
    __shared__ __align__(16) float sbt[96 * 36];
    const int tid = threadIdx.x, lane = tid & 31, wid = tid >> 5;
    const int bt = blockIdx.x >> 2, cq = blockIdx.x & 3;
    const int b0 = bt * 128, c0 = cq * 96;
    const int kk = tid & 31, row0 = tid >> 5;
    const int rslab = (wid >> 1) * 32, chalf = (wid & 1) * 48;

    float areg[16]; float4 breg[3];
    #define LOADA_F(KT)                                                        \
        _Pragma("unroll")                                                      \
        for (int j = 0; j < 16; ++j)                                           \
            areg[j] = g_ao[(size_t)(b0 + row0 + 8 * j) * 384 + (KT) + kk];

    LOADA_F(0); LOADB(fc_w, c0, 384, 0);
    float acc[48] = {};
    for (int t = 0; t < 12; ++t) {
        __syncthreads();
        STSA(); STSB();
        __syncthreads();
        if (t < 11) { LOADA_F((t + 1) * 32); LOADB(fc_w, c0, 384, (t + 1) * 32); }
        mma_warp2<6>(acc, saf + rslab * 36, sbt + chalf * 36, lane);
    }
    const int grp = lane >> 2, tig = lane & 3;
    const int r0 = b0 + rslab + grp;
    float tsv[4];
    #pragma unroll
    for (int s = 0; s < 4; ++s) tsv[s] = src_ts[r0 + 8 * s];
    #pragma unroll
    for (int s = 0; s < 4; ++s) {
        const int rr = r0 + 8 * s;
        const int ab = (s >> 1) * 24 + (s & 1) * 2;  // acc offset: slab*(6*4) + (row-in-frag)*2
        #pragma unroll
        for (int nt = 0; nt < 6; ++nt) {
            #pragma unroll
            for (int cc = 0; cc < 2; ++cc) {
                int col = c0 + chalf + nt * 8 + tig * 2 + cc;
                float v = acc[ab + nt * 4 + cc] + fc_b[col];
                if (col < 128) {
                    v += src[(size_t)rr * 128 + col];
                } else if (col >= 256) {
                    int d = col - 256;
                    v += __cosf(tsv[s] * freq[d] + phase[d]);
                }
                g_pre[(size_t)rr * 384 + col] = v;
            }
        }
    }
    #undef LOADA_F
}

// ---------------- k_mlp: two-pass LN + tensor-core MLP, 64 rows/block (R7 engine) ----------------
__global__ void __launch_bounds__(256) k_mlp(const float* __restrict__ src,
                                             const float* __restrict__ ln_g,
                                             const float* __restrict__ ln_b,
                                             const float* __restrict__ m1_w,
                                             const float* __restrict__ m1_b,
                                             const float* __restrict__ m2_w,
                                             const float* __restrict__ m2_b,
                                             float* __restrict__ y) {
    extern __shared__ __align__(16) float dynm[];
    float* saf  = dynm;                 // 2304
    float* sbt  = saf + 64 * 36;        // 4608
    float* hst  = sbt + 128 * 36;       // 4 x 2304
    float* smu  = hst + 4 * 2304;       // 64
    float* sinv = smu + 64;             // 64
    const int tid = threadIdx.x, lane = tid & 31, wid = tid >> 5;
    const int b0 = blockIdx.x * 64;
    const int kk = tid & 31, row0 = tid >> 5;

    for (int rr = 0; rr < 8; ++rr) {
        int row = wid * 8 + rr;
        const float* pr = g_pre + (size_t)(b0 + row) * 384;
        float s1 = 0.f, s2 = 0.f;
        #pragma unroll
        for (int t = 0; t < 12; ++t) {
            float v = pr[lane + 32 * t];
            s1 += v; s2 = fmaf(v, v, s2);
        }
        #pragma unroll
        for (int off = 16; off; off >>= 1) {
            s1 += __shfl_xor_sync(0xffffffffu, s1, off);
            s2 += __shfl_xor_sync(0xffffffffu, s2, off);
        }
        if (lane == 0) {
            float mu = s1 * (1.f / 384.f);
            float var = s2 * (1.f / 384.f) - mu * mu;
            smu[row] = mu;
            sinv[row] = rsqrtf(var + 1e-5f);
        }
    }
    __syncthreads();

    float areg[8]; float4 breg[4];
    #define LOADB4(W, KS, KT)                                                  \
        _Pragma("unroll")                                                      \
        for (int jj = 0; jj < 4; ++jj) {                                       \
            int qidx = tid + 256 * jj, col = qidx >> 3, q = qidx & 7;          \
            breg[jj] = *(const float4*)&(W)[(size_t)col * (KS) + (KT) + q * 4]; \
        }
    #define STSB4()                                                            \
        _Pragma("unroll")                                                      \
        for (int jj = 0; jj < 4; ++jj) {                                       \
            int qidx = tid + 256 * jj, col = qidx >> 3, q = qidx & 7;          \
            float4 v = breg[jj];                                               \
            v.x = __uint_as_float(tf32cvt(v.x)); v.y = __uint_as_float(tf32cvt(v.y)); \
            v.z = __uint_as_float(tf32cvt(v.z)); v.w = __uint_as_float(tf32cvt(v.w)); \
            *(float4*)&sbt[col * 36 + q * 4] = v;                              \
        }
    #define LOADA_X(KT) do {                                                   \
        int k_ = (KT) + kk;                                                    \
        if (k_ < 384) {                                                        \
            _Pragma("unroll")                                                  \
            for (int j = 0; j < 8; ++j)                                        \
                areg[j] = g_pre[(size_t)(b0 + row0 + 8 * j) * 384 + k_];       \
        } else {                                                               \
            int d_ = k_ - 384;                                                 \
            _Pragma("unroll")                                                  \
            for (int j = 0; j < 8; ++j)                                        \
                areg[j] = src[(size_t)(b0 + row0 + 8 * j) * 128 + d_];         \
        } } while (0)
    #define STSA_X(KT) do {                                                    \
        int k_ = (KT) + kk;                                                    \
        if (k_ < 384) {                                                        \
            float lng = ln_g[k_], lnb = ln_b[k_];                              \
            _Pragma("unroll")                                                  \
            for (int j = 0; j < 8; ++j) {                                      \
                int row = row0 + 8 * j;                                        \
                float v = (areg[j] - smu[row]) * sinv[row] * lng + lnb;        \
                saf[row * 36 + kk] = __uint_as_float(tf32cvt(v));              \
            }                                                                  \
        } else {                                                               \
            _Pragma("unroll")                                                  \
            for (int j = 0; j < 8; ++j)                                        \
                saf[(row0 + 8 * j) * 36 + kk] = __uint_as_float(tf32cvt(areg[j])); \
        } } while (0)

    const int grp = lane >> 2, tig = lane & 3;
    const int rslab = (wid >> 1) * 16, chalf = (wid & 1) * 64;
    const int r0 = rslab + grp;

    #define MMA_SCALAR(ACC, SA, SB, NTC)                                       \
        _Pragma("unroll")                                                      \
        for (int sub = 0; sub < 4; ++sub) {                                    \
            const int kb = sub * 8;                                            \
            const float* ap = (SA) + grp * 36 + kb + tig;                      \
            unsigned int a0 = __float_as_uint(ap[0]);                          \
            unsigned int a1 = __float_as_uint(ap[8 * 36]);                     \
            unsigned int a2 = __float_as_uint(ap[4]);                          \
            unsigned int a3 = __float_as_uint(ap[8 * 36 + 4]);                 \
            _Pragma("unroll")                                                  \
            for (int nt = 0; nt < (NTC); ++nt) {                               \
                const float* bp = (SB) + (nt * 8 + grp) * 36 + kb + tig;       \
                unsigned int b0_ = __float_as_uint(bp[0]);                     \
                unsigned int b1_ = __float_as_uint(bp[4]);                     \
                float* c = (ACC) + nt * 4;                                     \
                asm volatile(                                                  \
                    "mma.sync.aligned.m16n8k8.row.col.f32.tf32.tf32.f32 "      \
                    "{%0,%1,%2,%3}, {%4,%5,%6,%7}, {%8,%9}, {%0,%1,%2,%3};"    \
                    : "+f"(c[0]), "+f"(c[1]), "+f"(c[2]), "+f"(c[3])           \
                    : "r"(a0), "r"(a1), "r"(a2), "r"(a3), "r"(b0_), "r"(b1_)); \
            }                                                                  \
        }

    LOADA_X(0); LOADB4(m1_w, 512, 0);
    float acc[32] = {};
    for (int t = 0; t < 16; ++t) {
        __syncthreads();
        STSA_X(t * 32); STSB4();
        __syncthreads();
        if (t < 15) { LOADA_X((t + 1) * 32); LOADB4(m1_w, 512, (t + 1) * 32); }
        MMA_SCALAR(acc, saf + rslab * 36, sbt + chalf * 36, 8)
    }
    #pragma unroll
    for (int nt = 0; nt < 8; ++nt) {
        int col = chalf + nt * 8 + tig * 2;
        float b1a = m1_b[col], b1b = m1_b[col + 1];
        float* hb = hst + (col >> 5) * 2304 + (col & 31);
        hb[r0 * 36]           = __uint_as_float(tf32cvt(fmaxf(acc[nt*4+0] + b1a, 0.f)));
        hb[r0 * 36 + 1]       = __uint_as_float(tf32cvt(fmaxf(acc[nt*4+1] + b1b, 0.f)));
        hb[(r0 + 8) * 36]     = __uint_as_float(tf32cvt(fmaxf(acc[nt*4+2] + b1a, 0.f)));
        hb[(r0 + 8) * 36 + 1] = __uint_as_float(tf32cvt(fmaxf(acc[nt*4+3] + b1b, 0.f)));
    }
    #pragma unroll
    for (int i = 0; i < 32; ++i) acc[i] = 0.f;

    for (int t = 0; t < 4; ++t) {
        LOADB4(m2_w, 128, t * 32);
        __syncthreads();
        STSB4();
        __syncthreads();
        MMA_SCALAR(acc, hst + t * 2304 + rslab * 36, sbt + chalf * 36, 8)
    }
    #pragma unroll
    for (int nt = 0; nt < 8; ++nt) {
        int col = chalf + nt * 8 + tig * 2;
        float b2a = m2_b[col], b2b = m2_b[col + 1];
        *(float2*)&y[(size_t)(b0 + r0) * 128 + col] =
            make_float2(acc[nt*4+0] + b2a, acc[nt*4+1] + b2b);
        *(float2*)&y[(size_t)(b0 + r0 + 8) * 128 + col] =
            make_float2(acc[nt*4+2] + b2a, acc[nt*4+3] + b2b);
    }
    #undef LOADB4
    #undef STSB4
    #undef LOADA_X
    #undef STSA_X
    #undef MMA_SCALAR
}

// ---------------- launch ----------------
extern "C" void kernel_launch(void* const* d_in, const int* in_sizes, int n_in,
                              void* d_out, int out_size) {
    const float* src    = (const float*)d_in[0];
    const float* seq    = (const float*)d_in[1];
    const float* seq_e  = (const float*)d_in[2];
    const float* src_ts = (const float*)d_in[3];
    const float* seq_ts = (const float*)d_in[4];
    const unsigned int* mask = (const unsigned int*)d_in[5];
    const float* freq   = (const float*)d_in[6];
    const float* phase  = (const float*)d_in[7];
    const float* Wq     = (const float*)d_in[8];
    const float* Wk     = (const float*)d_in[9];
    const float* Wv     = (const float*)d_in[10];
    const float* fc_w   = (const float*)d_in[11];
    const float* fc_b   = (const float*)d_in[12];
    const float* ln_g   = (const float*)d_in[13];
    const float* ln_b   = (const float*)d_in[14];
    const float* m1_w   = (const float*)d_in[15];
    const float* m1_b   = (const float*)d_in[16];
    const float* m2_w   = (const float*)d_in[17];
    const float* m2_b   = (const float*)d_in[18];

    float* y_out = (float*)d_out;
    float* attn_out = y_out + (size_t)BB * DD;

    const int mlp_smem = (2304 + 4608 + 4 * 2304 + 128) * 4;   // 65024
    cudaFuncSetAttribute(k_mlp, cudaFuncAttributeMaxDynamicSharedMemorySize, mlp_smem);

    k_prepm <<<192, 256>>>(Wq, Wk);
    k_qt    <<<2048, 256>>>(src, src_ts, freq, phase);
    k_attn  <<<BB, 256>>>(seq, seq_e, seq_ts, mask, freq, phase, attn_out);
    k_vout  <<<512, 256>>>(Wv);
    k_fc    <<<512, 256>>>(src, src_ts, freq, phase, fc_w, fc_b);
    k_mlp   <<<256, 256, mlp_smem>>>(src, ln_g, ln_b, m1_w, m1_b, m2_w, m2_b, y_out);
}

// round 11
// speedup vs baseline: 1.3933x; 1.1531x over previous
#include <cuda_runtime.h>
#include <cuda_fp16.h>
#include <math.h>

#define BB 16384
#define NN 20
#define DD 128
#define HH 4
#define SCALE 0.1020620726159658f /* 1/sqrt(96) */

// ---------------- device scratch ----------------
__device__ __half g_qt[(size_t)BB * 1536];  // q-tilde (fp16)
__device__ __half g_c [(size_t)BB * 1536];  // context (fp16)
__device__ __half g_ao[(size_t)BB * 384];   // attn out pre-fc (fp16)
__device__ float  g_pre[(size_t)BB * 384];  // fc+bias+residual (fp32, pre-LN)
__device__ __half g_Mqk[1536 * 256];        // fused Wq*Wk matrix [j][k] (fp16)

// ---------------- prep: M_qk[j][k] = sum_d Wq[h*96+d][keff] * Wk[h*96+d][jj] ----------------
__global__ void __launch_bounds__(256) k_prepm(const float* __restrict__ Wq,
                                               const float* __restrict__ Wk) {
    __shared__ float wk[8 * 96];
    const int tid = threadIdx.x;
    const int j0 = blockIdx.x * 8;
    const int h = j0 / 384;
    const int jj0 = j0 - h * 384;

    for (int i = tid; i < 768; i += 256) {
        int jo = i / 96, d = i - jo * 96;
        wk[jo * 96 + d] = Wk[(size_t)(h * 96 + d) * 384 + jj0 + jo];
    }
    __syncthreads();

    const int k = tid;
    const int keff = (k < 128) ? k : k + 128;
    float acc[8] = {};
    for (int d = 0; d < 96; ++d) {
        float wq = __ldg(&Wq[(size_t)(h * 96 + d) * 384 + keff]);
        #pragma unroll
        for (int jo = 0; jo < 8; ++jo)
            acc[jo] = fmaf(wq, wk[jo * 96 + d], acc[jo]);
    }
    #pragma unroll
    for (int jo = 0; jo < 8; ++jo)
        g_Mqk[(size_t)(j0 + jo) * 256 + k] = __float2half_rn(acc[jo]);
}

// ---------- fp16 mma m16n8k16 ----------
__device__ __forceinline__ void mma16(float* c, unsigned a0, unsigned a1, unsigned a2,
                                      unsigned a3, unsigned b0, unsigned b1) {
    asm volatile(
        "mma.sync.aligned.m16n8k16.row.col.f32.f16.f16.f32 "
        "{%0,%1,%2,%3}, {%4,%5,%6,%7}, {%8,%9}, {%0,%1,%2,%3};"
        : "+f"(c[0]), "+f"(c[1]), "+f"(c[2]), "+f"(c[3])
        : "r"(a0), "r"(a1), "r"(a2), "r"(a3), "r"(b0), "r"(b1));
}

// A smem: [row][k] halves, stride 40 (conflict-free: banks = row*20+tig distinct)
// B smem: [col][k] halves, stride 40
// warp tile 32 rows x NT*8 cols; B fragments reused across 2 A slabs
template<int NT>
__device__ __forceinline__ void mma16_warp2(float* acc, const __half* sa, const __half* sbt,
                                            int lane) {
    const int grp = lane >> 2, tig = lane & 3;
    #pragma unroll
    for (int ks = 0; ks < 2; ++ks) {
        const __half* ap0 = sa + grp * 40 + ks * 16 + tig * 2;
        const __half* ap1 = ap0 + 16 * 40;
        unsigned a00 = *(const unsigned*)ap0;
        unsigned a01 = *(const unsigned*)(ap0 + 320);
        unsigned a02 = *(const unsigned*)(ap0 + 8);
        unsigned a03 = *(const unsigned*)(ap0 + 328);
        unsigned a10 = *(const unsigned*)ap1;
        unsigned a11 = *(const unsigned*)(ap1 + 320);
        unsigned a12 = *(const unsigned*)(ap1 + 8);
        unsigned a13 = *(const unsigned*)(ap1 + 328);
        #pragma unroll
        for (int nt = 0; nt < NT; ++nt) {
            const __half* bp = sbt + (nt * 8 + grp) * 40 + ks * 16 + tig * 2;
            unsigned b0 = *(const unsigned*)bp;
            unsigned b1 = *(const unsigned*)(bp + 8);
            mma16(acc + nt * 4, a00, a01, a02, a03, b0, b1);
            mma16(acc + (NT + nt) * 4, a10, a11, a12, a13, b0, b1);
        }
    }
}

// single-slab variant (16 rows x NT*8 cols)
template<int NT>
__device__ __forceinline__ void mma16_warp(float* acc, const __half* sa, const __half* sbt,
                                           int lane) {
    const int grp = lane >> 2, tig = lane & 3;
    #pragma unroll
    for (int ks = 0; ks < 2; ++ks) {
        const __half* ap0 = sa + grp * 40 + ks * 16 + tig * 2;
        unsigned a00 = *(const unsigned*)ap0;
        unsigned a01 = *(const unsigned*)(ap0 + 320);
        unsigned a02 = *(const unsigned*)(ap0 + 8);
        unsigned a03 = *(const unsigned*)(ap0 + 328);
        #pragma unroll
        for (int nt = 0; nt < NT; ++nt) {
            const __half* bp = sbt + (nt * 8 + grp) * 40 + ks * 16 + tig * 2;
            unsigned b0 = *(const unsigned*)bp;
            unsigned b1 = *(const unsigned*)(bp + 8);
            mma16(acc + nt * 4, a00, a01, a02, a03, b0, b1);
        }
    }
}

// fp32-weight B loader (96 cols x 32 k; 3 float4/thread) + fp16 stager
#define LOADB(W, COLB, KS, KT)                                                \
    _Pragma("unroll")                                                         \
    for (int jj = 0; jj < 3; ++jj) {                                          \
        int qidx = tid + 256 * jj, col = qidx >> 3, q = qidx & 7;             \
        breg[jj] = *(const float4*)&(W)[(size_t)((COLB) + col) * (KS) + (KT) + q * 4]; \
    }
#define STSB()                                                                \
    _Pragma("unroll")                                                         \
    for (int jj = 0; jj < 3; ++jj) {                                          \
        int qidx = tid + 256 * jj, col = qidx >> 3, q = qidx & 7;             \
        float4 v = breg[jj];                                                  \
        *(__half2*)&sbt[col * 40 + q * 4]     = __floats2half2_rn(v.x, v.y);  \
        *(__half2*)&sbt[col * 40 + q * 4 + 2] = __floats2half2_rn(v.z, v.w);  \
    }
// fp16-global A loader/stager (128 rows x 32 k): thread (rowb=tid>>4, kp=tid&15)
#define LOADA_H(SRC, RSTRIDE, ROWB, KT)                                       \
    _Pragma("unroll")                                                         \
    for (int j = 0; j < 8; ++j)                                               \
        aregu[j] = *(const unsigned*)&(SRC)[(size_t)((ROWB) + rowb + 16 * j) * (RSTRIDE) + (KT) + 2 * kp];
#define STSA_H()                                                              \
    _Pragma("unroll")                                                         \
    for (int j = 0; j < 8; ++j)                                               \
        *(unsigned*)&saf[(rowb + 16 * j) * 40 + 2 * kp] = aregu[j];

// ---------------- k_qt: g_qt[B x 1536] = A_eff[B x 256] @ M_qk^T ----------------
__global__ void __launch_bounds__(256, 2) k_qt(const float* __restrict__ src,
                                               const float* __restrict__ src_ts,
                                               const float* __restrict__ freq,
                                               const float* __restrict__ phase) {
    __shared__ __align__(16) __half saf[128 * 40];
    __shared__ __align__(16) __half sbt[96 * 40];
    __shared__ float sts[128];
    const int tid = threadIdx.x, lane = tid & 31, wid = tid >> 5;
    const int bt = blockIdx.x >> 4, cq = blockIdx.x & 15;
    const int b0 = bt * 128, c0 = cq * 96;
    const int kk = tid & 31, row0 = tid >> 5;
    const int rslab = (wid >> 1) * 32, chalf = (wid & 1) * 48;

    if (tid < 128) sts[tid] = src_ts[b0 + tid];
    __syncthreads();

    float areg[16]; uint2 bregu[3];
    #define LOADA_QT(KT) do {                                                 \
        int m = (KT) + kk;                                                    \
        if (m < 128) {                                                        \
            _Pragma("unroll")                                                 \
            for (int j = 0; j < 16; ++j)                                      \
                areg[j] = src[(size_t)(b0 + row0 + 8 * j) * 128 + m];         \
        } else {                                                              \
            float f = freq[m - 128], ph = phase[m - 128];                     \
            _Pragma("unroll")                                                 \
            for (int j = 0; j < 16; ++j)                                      \
                areg[j] = __cosf(sts[row0 + 8 * j] * f + ph);                 \
        } } while (0)
    #define LOADB_QT(KT)                                                      \
        _Pragma("unroll")                                                     \
        for (int jj = 0; jj < 3; ++jj) {                                      \
            int qidx = tid + 256 * jj, col = qidx >> 3, q = qidx & 7;         \
            bregu[jj] = *(const uint2*)&g_Mqk[(size_t)(c0 + col) * 256 + (KT) + q * 4]; \
        }
    #define STSA_QT()                                                         \
        _Pragma("unroll")                                                     \
        for (int j = 0; j < 16; ++j)                                          \
            saf[(row0 + 8 * j) * 40 + kk] = __float2half_rn(areg[j]);
    #define STSB_QT()                                                         \
        _Pragma("unroll")                                                     \
        for (int jj = 0; jj < 3; ++jj) {                                      \
            int qidx = tid + 256 * jj, col = qidx >> 3, q = qidx & 7;         \
            *(uint2*)&sbt[col * 40 + q * 4] = bregu[jj];                      \
        }

    LOADA_QT(0); LOADB_QT(0);
    float acc[48] = {};
    for (int t = 0; t < 8; ++t) {
        __syncthreads();
        STSA_QT(); STSB_QT();
        __syncthreads();
        if (t < 7) { LOADA_QT((t + 1) * 32); LOADB_QT((t + 1) * 32); }
        mma16_warp2<6>(acc, saf + rslab * 40, sbt + chalf * 40, lane);
    }
    const int grp = lane >> 2, tig = lane & 3;
    const int r0 = b0 + rslab + grp;
    #pragma unroll
    for (int nt = 0; nt < 6; ++nt) {
        int j = c0 + chalf + nt * 8 + tig * 2;
        *(__half2*)&g_qt[(size_t)r0 * 1536 + j]        = __floats2half2_rn(acc[nt*4+0], acc[nt*4+1]);
        *(__half2*)&g_qt[(size_t)(r0 + 8) * 1536 + j]  = __floats2half2_rn(acc[nt*4+2], acc[nt*4+3]);
        *(__half2*)&g_qt[(size_t)(r0 + 16) * 1536 + j] = __floats2half2_rn(acc[(6+nt)*4+0], acc[(6+nt)*4+1]);
        *(__half2*)&g_qt[(size_t)(r0 + 24) * 1536 + j] = __floats2half2_rn(acc[(6+nt)*4+2], acc[(6+nt)*4+3]);
    }
    #undef LOADA_QT
    #undef LOADB_QT
    #undef STSA_QT
    #undef STSB_QT
}

// ---------------- attention core: one block per batch element ----------------
__global__ void __launch_bounds__(256) k_attn(const float* __restrict__ seq,
                                              const float* __restrict__ seq_e,
                                              const float* __restrict__ seq_ts,
                                              const unsigned int* __restrict__ mask,
                                              const float* __restrict__ freq,
                                              const float* __restrict__ phase,
                                              float* __restrict__ attn_out) {
    __shared__ float kin[NN * 384];
    __shared__ float qts[1536];
    __shared__ float sc[HH][NN];
    __shared__ float pp[HH][NN];
    const int b = blockIdx.x;
    const int tid = threadIdx.x;
    const int w = tid >> 5, lane = tid & 31;

    const float4* seq4   = (const float4*)seq;
    const float4* seq_e4 = (const float4*)seq_e;
    for (int idx = tid; idx < NN * 32; idx += 256) {
        int n = idx >> 5, q = idx & 31;
        float4 a = seq4  [((size_t)b * NN + n) * 32 + q];
        float4 e = seq_e4[((size_t)b * NN + n) * 32 + q];
        *(float4*)&kin[n * 384 + q * 4]       = a;
        *(float4*)&kin[n * 384 + 128 + q * 4] = e;
    }
    for (int idx = tid; idx < NN * 128; idx += 256) {
        int n = idx >> 7, d = idx & 127;
        kin[n * 384 + 256 + d] = __cosf(seq_ts[b * NN + n] * freq[d] + phase[d]);
    }
    const __half2* qt2 = (const __half2*)(g_qt + (size_t)b * 1536);
    for (int idx = tid; idx < 768; idx += 256) {
        float2 f = __half22float2(qt2[idx]);
        qts[idx * 2]     = f.x;
        qts[idx * 2 + 1] = f.y;
    }
    __syncthreads();

    for (int p = w; p < HH * NN; p += 8) {
        int h = p / NN, n = p - h * NN;
        float partial = 0.f;
        #pragma unroll
        for (int t = 0; t < 12; ++t)
            partial = fmaf(qts[h * 384 + lane + 32 * t], kin[n * 384 + lane + 32 * t], partial);
        #pragma unroll
        for (int off = 16; off; off >>= 1)
            partial += __shfl_xor_sync(0xffffffffu, partial, off);
        if (lane == 0) {
            float s = partial * SCALE;
            if (mask[b * NN + n] != 0u) s = -1.0e10f;
            sc[h][n] = s;
        }
    }
    __syncthreads();

    if (w < HH) {
        float v = (lane < NN) ? sc[w][lane] : -3.0e38f;
        float mx = v;
        #pragma unroll
        for (int off = 16; off; off >>= 1)
            mx = fmaxf(mx, __shfl_xor_sync(0xffffffffu, mx, off));
        float e = (lane < NN) ? expf(v - mx) : 0.f;
        float s = e;
        #pragma unroll
        for (int off = 16; off; off >>= 1)
            s += __shfl_xor_sync(0xffffffffu, s, off);
        float prob = e / s;
        if (lane < NN) {
            pp[w][lane] = prob;
            attn_out[((size_t)w * BB + b) * NN + lane] = prob;
        }
    }
    __syncthreads();

    for (int idx = tid; idx < 1536; idx += 256) {
        int h = idx / 384, j = idx - h * 384;
        float s = 0.f;
        #pragma unroll
        for (int n = 0; n < NN; ++n)
            s = fmaf(pp[h][n], kin[n * 384 + j], s);
        g_c[(size_t)b * 1536 + idx] = __float2half_rn(s);
    }
}

// ---------------- k_vout: g_ao head slab = g_c_h[B x 384] @ Wv_h^T ----------------
__global__ void __launch_bounds__(256, 2) k_vout(const float* __restrict__ Wv) {
    __shared__ __align__(16) __half saf[128 * 40];
    __shared__ __align__(16) __half sbt[96 * 40];
    const int tid = threadIdx.x, lane = tid & 31, wid = tid >> 5;
    const int bt = blockIdx.x >> 2, h = blockIdx.x & 3;
    const int b0 = bt * 128;
    const int rowb = tid >> 4, kp = tid & 15;
    const int rslab = (wid >> 1) * 32, chalf = (wid & 1) * 48;

    unsigned aregu[8]; float4 breg[3];
    LOADA_H(g_c, 1536, b0, h * 384 + 0); LOADB(Wv, h * 96, 384, 0);
    float acc[48] = {};
    for (int t = 0; t < 12; ++t) {
        __syncthreads();
        STSA_H(); STSB();
        __syncthreads();
        if (t < 11) {
            LOADA_H(g_c, 1536, b0, h * 384 + (t + 1) * 32);
            LOADB(Wv, h * 96, 384, (t + 1) * 32);
        }
        mma16_warp2<6>(acc, saf + rslab * 40, sbt + chalf * 40, lane);
    }
    const int grp = lane >> 2, tig = lane & 3;
    const int r0 = b0 + rslab + grp;
    #pragma unroll
    for (int nt = 0; nt < 6; ++nt) {
        int col = h * 96 + chalf + nt * 8 + tig * 2;
        *(__half2*)&g_ao[(size_t)r0 * 384 + col]        = __floats2half2_rn(acc[nt*4+0], acc[nt*4+1]);
        *(__half2*)&g_ao[(size_t)(r0 + 8) * 384 + col]  = __floats2half2_rn(acc[nt*4+2], acc[nt*4+3]);
        *(__half2*)&g_ao[(size_t)(r0 + 16) * 384 + col] = __floats2half2_rn(acc[(6+nt)*4+0], acc[(6+nt)*4+1]);
        *(__half2*)&g_ao[(size_t)(r0 + 24) * 384 + col] = __floats2half2_rn(acc[(6+nt)*4+2], acc[(6+nt)*4+3]);
    }
}

// ---------------- k_fc: g_pre = g_ao @ fc_w^T + b + residual ----------------
__global__ void __launch_bounds__(256, 2) k_fc(const float* __restrict__ src,
                                               const float* __restrict__ src_ts,
                                               const float* __restrict__ freq,
                                               const float* __restrict__ phase,
                                               const float* __restrict__ fc_w,
                                               const float* __restrict__ fc_b) {
    __shared__ __align__(16) __half saf[128 * 40];
    __shared__ __align__(16) __half sbt[96 * 40];
    const int tid = threadIdx.x, lane = tid & 31, wid = tid >> 5;
    const int bt = blockIdx.x >> 2, cq = blockIdx.x & 3;
    const int b0 = bt * 128, c0 = cq * 96;
    const int rowb = tid >> 4, kp = tid & 15;
    const int rslab = (wid >> 1) * 32, chalf = (wid & 1) * 48;

    unsigned aregu[8]; float4 breg[3];
    LOADA_H(g_ao, 384, b0, 0); LOADB(fc_w, c0, 384, 0);
    float acc[48] = {};
    for (int t = 0; t < 12; ++t) {
        __syncthreads();
        STSA_H(); STSB();
        __syncthreads();
        if (t < 11) {
            LOADA_H(g_ao, 384, b0, (t + 1) * 32);
            LOADB(fc_w, c0, 384, (t + 1) * 32);
        }
        mma16_warp2<6>(acc, saf + rslab * 40, sbt + chalf * 40, lane);
    }
    const int grp = lane >> 2, tig = lane & 3;
    const int r0 = b0 + rslab + grp;
    float tsv[4];
    #pragma unroll
    for (int s = 0; s < 4; ++s) tsv[s] = src_ts[r0 + 8 * s];
    #pragma unroll
    for (int s = 0; s < 4; ++s) {
        const int rr = r0 + 8 * s;
        const int ab = (s >> 1) * 24 + (s & 1) * 2;
        #pragma unroll
        for (int nt = 0; nt < 6; ++nt) {
            #pragma unroll
            for (int cc = 0; cc < 2; ++cc) {
                int col = c0 + chalf + nt * 8 + tig * 2 + cc;
                float v = acc[ab + nt * 4 + cc] + fc_b[col];
                if (col < 128) {
                    v += src[(size_t)rr * 128 + col];
                } else if (col >= 256) {
                    int d = col - 256;
                    v += __cosf(tsv[s] * freq[d] + phase[d]);
                }
                g_pre[(size_t)rr * 384 + col] = v;
            }
        }
    }
}

// ---------------- k_mlp: two-pass LN + fp16 tensor-core MLP, 64 rows/block ----------------
__global__ void __launch_bounds__(256) k_mlp(const float* __restrict__ src,
                                             const float* __restrict__ ln_g,
                                             const float* __restrict__ ln_b,
                                             const float* __restrict__ m1_w,
                                             const float* __restrict__ m1_b,
                                             const float* __restrict__ m2_w,
                                             const float* __restrict__ m2_b,
                                             float* __restrict__ y) {
    __shared__ __align__(16) __half saf[64 * 40];        // 5120 B
    __shared__ __align__(16) __half sbtm[128 * 40];      // 10240 B
    __shared__ __align__(16) __half hst[4 * 64 * 40];    // 20480 B
    __shared__ float smu[64], sinv[64];
    const int tid = threadIdx.x, lane = tid & 31, wid = tid >> 5;
    const int b0 = blockIdx.x * 64;
    const int kk = tid & 31, row0 = tid >> 5;

    // pass 1: LN stats
    for (int rr = 0; rr < 8; ++rr) {
        int row = wid * 8 + rr;
        const float* pr = g_pre + (size_t)(b0 + row) * 384;
        float s1 = 0.f, s2 = 0.f;
        #pragma unroll
        for (int t = 0; t < 12; ++t) {
            float v = pr[lane + 32 * t];
            s1 += v; s2 = fmaf(v, v, s2);
        }
        #pragma unroll
        for (int off = 16; off; off >>= 1) {
            s1 += __shfl_xor_sync(0xffffffffu, s1, off);
            s2 += __shfl_xor_sync(0xffffffffu, s2, off);
        }
        if (lane == 0) {
            float mu = s1 * (1.f / 384.f);
            float var = s2 * (1.f / 384.f) - mu * mu;
            smu[row] = mu;
            sinv[row] = rsqrtf(var + 1e-5f);
        }
    }
    __syncthreads();

    float areg[8]; float4 breg4[4];
    #define LOADB4(W, KS, KT)                                                  \
        _Pragma("unroll")                                                      \
        for (int jj = 0; jj < 4; ++jj) {                                       \
            int qidx = tid + 256 * jj, col = qidx >> 3, q = qidx & 7;          \
            breg4[jj] = *(const float4*)&(W)[(size_t)col * (KS) + (KT) + q * 4]; \
        }
    #define STSB4()                                                            \
        _Pragma("unroll")                                                      \
        for (int jj = 0; jj < 4; ++jj) {                                       \
            int qidx = tid + 256 * jj, col = qidx >> 3, q = qidx & 7;          \
            float4 v = breg4[jj];                                              \
            *(__half2*)&sbtm[col * 40 + q * 4]     = __floats2half2_rn(v.x, v.y); \
            *(__half2*)&sbtm[col * 40 + q * 4 + 2] = __floats2half2_rn(v.z, v.w); \
        }
    #define LOADA_X(KT) do {                                                   \
        int k_ = (KT) + kk;                                                    \
        if (k_ < 384) {                                                        \
            _Pragma("unroll")                                                  \
            for (int j = 0; j < 8; ++j)                                        \
                areg[j] = g_pre[(size_t)(b0 + row0 + 8 * j) * 384 + k_];       \
        } else {                                                               \
            int d_ = k_ - 384;                                                 \
            _Pragma("unroll")                                                  \
            for (int j = 0; j < 8; ++j)                                        \
                areg[j] = src[(size_t)(b0 + row0 + 8 * j) * 128 + d_];         \
        } } while (0)
    #define STSA_X(KT) do {                                                    \
        int k_ = (KT) + kk;                                                    \
        if (k_ < 384) {                                                        \
            float lng = ln_g[k_], lnb = ln_b[k_];                              \
            _Pragma("unroll")                                                  \
            for (int j = 0; j < 8; ++j) {                                      \
                int row = row0 + 8 * j;                                        \
                float v = (areg[j] - smu[row]) * sinv[row] * lng + lnb;        \
                saf[row * 40 + kk] = __float2half_rn(v);                       \
            }                                                                  \
        } else {                                                               \
            _Pragma("unroll")                                                  \
            for (int j = 0; j < 8; ++j)                                        \
                saf[(row0 + 8 * j) * 40 + kk] = __float2half_rn(areg[j]);      \
        } } while (0)

    const int grp = lane >> 2, tig = lane & 3;
    const int rslab = (wid >> 1) * 16, chalf = (wid & 1) * 64;
    const int r0 = rslab + grp;

    // GEMM1: h(64x128) = relu(xln(64x512) @ m1_w^T + b1), 16 K-tiles
    LOADA_X(0); LOADB4(m1_w, 512, 0);
    float acc[32] = {};
    for (int t = 0; t < 16; ++t) {
        __syncthreads();
        STSA_X(t * 32); STSB4();
        __syncthreads();
        if (t < 15) { LOADA_X((t + 1) * 32); LOADB4(m1_w, 512, (t + 1) * 32); }
        mma16_warp<8>(acc, saf + rslab * 40, sbtm + chalf * 40, lane);
    }
    // relu+bias -> hst (fp16), 4 K-tile A buffers of 64 rows x 40 halves
    #pragma unroll
    for (int nt = 0; nt < 8; ++nt) {
        int col = chalf + nt * 8 + tig * 2;
        float b1a = m1_b[col], b1b = m1_b[col + 1];
        __half* hb = hst + (col >> 5) * 2560 + (col & 31);
        *(__half2*)&hb[r0 * 40] =
            __floats2half2_rn(fmaxf(acc[nt*4+0] + b1a, 0.f), fmaxf(acc[nt*4+1] + b1b, 0.f));
        *(__half2*)&hb[(r0 + 8) * 40] =
            __floats2half2_rn(fmaxf(acc[nt*4+2] + b1a, 0.f), fmaxf(acc[nt*4+3] + b1b, 0.f));
    }
    #pragma unroll
    for (int i = 0; i < 32; ++i) acc[i] = 0.f;

    // GEMM2: y = h @ m2_w^T + b2, 4 K-tiles
    for (int t = 0; t < 4; ++t) {
        LOADB4(m2_w, 128, t * 32);
        __syncthreads();
        STSB4();
        __syncthreads();
        mma16_warp<8>(acc, hst + t * 2560 + rslab * 40, sbtm + chalf * 40, lane);
    }
    #pragma unroll
    for (int nt = 0; nt < 8; ++nt) {
        int col = chalf + nt * 8 + tig * 2;
        float b2a = m2_b[col], b2b = m2_b[col + 1];
        *(float2*)&y[(size_t)(b0 + r0) * 128 + col] =
            make_float2(acc[nt*4+0] + b2a, acc[nt*4+1] + b2b);
        *(float2*)&y[(size_t)(b0 + r0 + 8) * 128 + col] =
            make_float2(acc[nt*4+2] + b2a, acc[nt*4+3] + b2b);
    }
    #undef LOADB4
    #undef STSB4
    #undef LOADA_X
    #undef STSA_X
}

// ---------------- launch ----------------
extern "C" void kernel_launch(void* const* d_in, const int* in_sizes, int n_in,
                              void* d_out, int out_size) {
    const float* src    = (const float*)d_in[0];
    const float* seq    = (const float*)d_in[1];
    const float* seq_e  = (const float*)d_in[2];
    const float* src_ts = (const float*)d_in[3];
    const float* seq_ts = (const float*)d_in[4];
    const unsigned int* mask = (const unsigned int*)d_in[5];
    const float* freq   = (const float*)d_in[6];
    const float* phase  = (const float*)d_in[7];
    const float* Wq     = (const float*)d_in[8];
    const float* Wk     = (const float*)d_in[9];
    const float* Wv     = (const float*)d_in[10];
    const float* fc_w   = (const float*)d_in[11];
    const float* fc_b   = (const float*)d_in[12];
    const float* ln_g   = (const float*)d_in[13];
    const float* ln_b   = (const float*)d_in[14];
    const float* m1_w   = (const float*)d_in[15];
    const float* m1_b   = (const float*)d_in[16];
    const float* m2_w   = (const float*)d_in[17];
    const float* m2_b   = (const float*)d_in[18];

    float* y_out = (float*)d_out;
    float* attn_out = y_out + (size_t)BB * DD;

    k_prepm <<<192, 256>>>(Wq, Wk);
    k_qt    <<<2048, 256>>>(src, src_ts, freq, phase);
    k_attn  <<<BB, 256>>>(seq, seq_e, seq_ts, mask, freq, phase, attn_out);
    k_vout  <<<512, 256>>>(Wv);
    k_fc    <<<512, 256>>>(src, src_ts, freq, phase, fc_w, fc_b);
    k_mlp   <<<256, 256>>>(src, ln_g, ln_b, m1_w, m1_b, m2_w, m2_b, y_out);
}